// round 16
// baseline (speedup 1.0000x reference)
#include <cuda_runtime.h>
#include <cuda_fp16.h>
#include <cstdint>
#include <math.h>

#define B_ 2
#define L_ 2048
#define E_ 1024
#define H_ 8
#define D_ 128

// Scratch (allocation-free rule: __device__ globals)
__device__ __half g_Aq[B_ * L_ * E_];   // fp16 copies of activations
__device__ __half g_Ak[B_ * L_ * E_];
__device__ __half g_Av[B_ * L_ * E_];
__device__ __half g_Wqh[E_ * E_];       // fp16 copies of weights
__device__ __half g_Wkh[E_ * E_];
__device__ __half g_Wvh[E_ * E_];
__device__ __half g_Woh[E_ * E_];
__device__ __half g_Qh[B_ * L_ * E_];   // projection outputs
__device__ __half g_Kh[B_ * L_ * E_];
__device__ __half g_Vh[B_ * L_ * E_];
__device__ __half g_Ch[B_ * L_ * E_];   // attention context (fp16)

__constant__ int c_anchors[10] = {204, 409, 614, 781, 1023, 1265, 1432, 1637, 1842, 2047};

// ===========================================================================
// helpers
// ===========================================================================
__device__ __forceinline__ uint32_t smem_u32(const void* p) {
    uint32_t a;
    asm("{ .reg .u64 t; cvta.to.shared.u64 t, %1; cvt.u32.u64 %0, t; }" : "=r"(a) : "l"(p));
    return a;
}

__device__ __forceinline__ uint32_t pack_f16x2(float x0, float x1) {
    uint32_t r;
    asm("cvt.rn.f16x2.f32 %0, %2, %1;" : "=r"(r) : "f"(x0), "f"(x1));
    return r;
}

__device__ __forceinline__ void ldsm4(uint32_t* r, uint32_t addr) {
    asm volatile("ldmatrix.sync.aligned.m8n8.x4.shared.b16 {%0,%1,%2,%3}, [%4];"
                 : "=r"(r[0]), "=r"(r[1]), "=r"(r[2]), "=r"(r[3]) : "r"(addr));
}

__device__ __forceinline__ void ldsm4t(uint32_t* r, uint32_t addr) {
    asm volatile("ldmatrix.sync.aligned.m8n8.x4.trans.shared.b16 {%0,%1,%2,%3}, [%4];"
                 : "=r"(r[0]), "=r"(r[1]), "=r"(r[2]), "=r"(r[3]) : "r"(addr));
}

__device__ __forceinline__ void mma_f16(float* d, const uint32_t* a, const uint32_t* b) {
    asm volatile(
        "mma.sync.aligned.m16n8k16.row.col.f32.f16.f16.f32 "
        "{%0,%1,%2,%3}, {%4,%5,%6,%7}, {%8,%9}, {%0,%1,%2,%3};"
        : "+f"(d[0]), "+f"(d[1]), "+f"(d[2]), "+f"(d[3])
        : "r"(a[0]), "r"(a[1]), "r"(a[2]), "r"(a[3]), "r"(b[0]), "r"(b[1]));
}

#define CP16(dst, src) \
    asm volatile("cp.async.cg.shared.global [%0], [%1], 16;" :: "r"(dst), "l"(src) : "memory")

// ===========================================================================
// Mega-convert: all fp32 inputs -> fp16 in one launch (16M floats).
// Identical rounding to what the GEMM staging did before -> rel_err unchanged.
// ===========================================================================
#define N_ACT  1048576           // float4 count per activation (2*2048*1024/4)
#define N_WT   262144            // float4 count per weight (1024*1024/4)

__global__ __launch_bounds__(256)
void convert_all_kernel(const float4* __restrict__ q, const float4* __restrict__ k,
                        const float4* __restrict__ v, const float4* __restrict__ wq,
                        const float4* __restrict__ wk, const float4* __restrict__ wv,
                        const float4* __restrict__ wo,
                        uint2* __restrict__ aq, uint2* __restrict__ ak, uint2* __restrict__ av,
                        uint2* __restrict__ wqh, uint2* __restrict__ wkh,
                        uint2* __restrict__ wvh, uint2* __restrict__ woh) {
    int i = blockIdx.x * 256 + threadIdx.x;
    const float4* src; uint2* dst; int off;
    if (i < 3 * N_ACT) {
        if (i < N_ACT)            { src = q; dst = aq; off = i; }
        else if (i < 2 * N_ACT)   { src = k; dst = ak; off = i - N_ACT; }
        else                      { src = v; dst = av; off = i - 2 * N_ACT; }
    } else {
        int j = i - 3 * N_ACT;
        if (j < N_WT)             { src = wq; dst = wqh; off = j; }
        else if (j < 2 * N_WT)    { src = wk; dst = wkh; off = j - N_WT; }
        else if (j < 3 * N_WT)    { src = wv; dst = wvh; off = j - 2 * N_WT; }
        else                      { src = wo; dst = woh; off = j - 3 * N_WT; }
    }
    float4 x = src[off];
    dst[off] = make_uint2(pack_f16x2(x.x, x.y), pack_f16x2(x.z, x.w));
}

// ===========================================================================
// GEMM v3: fp16 inputs, cp.async double-buffered staging, occupancy 2.
//   C = A @ W^T + bias.  CTA 128x128, 8 warps (2m x 4n), BK=32.
// Stage: A(10240B) + W(10240B), 2 stages = 40960B static smem.
// ===========================================================================
#define LDA 80
#define OP_B 10240               // one operand per stage
#define STAGE_B 20480

template <typename OutT>
__global__ __launch_bounds__(256, 2)
void gemm_h_kernel(const __half* __restrict__ A, const __half* __restrict__ W,
                   const float* __restrict__ bias, OutT* __restrict__ Cout) {
    __shared__ __align__(16) uint8_t sm[2 * STAGE_B];
    uint32_t sb = smem_u32(sm);

    int tid = threadIdx.x;
    int lane = tid & 31;
    int wid = tid >> 5;
    int warpM = wid >> 2;
    int warpN = wid & 3;

    const __half* Ag = A + (size_t)blockIdx.y * 128 * 1024;
    const __half* Wg = W + (size_t)blockIdx.x * 128 * 1024;

    int srow = tid >> 1;         // 0..127
    int hf = tid & 1;            // which 32B half of the 64B row

    float acc[4][4][4];
#pragma unroll
    for (int f = 0; f < 4; ++f)
#pragma unroll
        for (int g = 0; g < 4; ++g)
#pragma unroll
            for (int r = 0; r < 4; ++r) acc[f][g][r] = 0.0f;

    uint32_t aRow = (uint32_t)(warpM * 64) + (lane & 15);
    uint32_t aAddrBase = aRow * LDA + ((lane >> 4) << 4);
    uint32_t bRow = (uint32_t)(warpN * 32) + (lane & 7) + ((lane >> 4) << 3);
    uint32_t bAddrBase = bRow * LDA + (((lane >> 3) & 1) << 4);

    // stage chunk kt into stage st
    auto stage = [&](int kt, int st) {
        uint32_t dA = sb + (uint32_t)st * STAGE_B + (uint32_t)srow * LDA + hf * 32;
        uint32_t dW = dA + OP_B;
        const __half* sA = Ag + (size_t)srow * 1024 + kt * 32 + hf * 16;
        const __half* sW = Wg + (size_t)srow * 1024 + kt * 32 + hf * 16;
        CP16(dA, sA); CP16(dA + 16, sA + 8);
        CP16(dW, sW); CP16(dW + 16, sW + 8);
        asm volatile("cp.async.commit_group;" ::: "memory");
    };

    stage(0, 0);

    for (int kt = 0; kt < 32; ++kt) {
        if (kt < 31) {
            stage(kt + 1, (kt + 1) & 1);
            asm volatile("cp.async.wait_group 1;" ::: "memory");
        } else {
            asm volatile("cp.async.wait_group 0;" ::: "memory");
        }
        __syncthreads();

        uint32_t sbA = sb + (uint32_t)(kt & 1) * STAGE_B;
        uint32_t sbW = sbA + OP_B;
#pragma unroll
        for (int ks = 0; ks < 2; ++ks) {
            uint32_t koff = ks * 32;
            uint32_t bF[2][4];
            ldsm4(bF[0], sbW + bAddrBase + koff);
            ldsm4(bF[1], sbW + bAddrBase + 16 * LDA + koff);
#pragma unroll
            for (int f = 0; f < 4; ++f) {
                uint32_t aF[4];
                ldsm4(aF, sbA + aAddrBase + (uint32_t)(f * 16) * LDA + koff);
#pragma unroll
                for (int g = 0; g < 4; ++g)
                    mma_f16(acc[f][g], aF, &bF[g >> 1][(g & 1) * 2]);
            }
        }
        __syncthreads();
    }

    int crow = blockIdx.y * 128 + warpM * 64 + (lane >> 2);
    int ccol0 = blockIdx.x * 128 + warpN * 32 + (lane & 3) * 2;
#pragma unroll
    for (int g = 0; g < 4; ++g) {
        int c = ccol0 + g * 8;
        float2 bv = *(const float2*)(bias + c);
#pragma unroll
        for (int f = 0; f < 4; ++f) {
            int r = crow + f * 16;
            float o00 = acc[f][g][0] + bv.x, o01 = acc[f][g][1] + bv.y;
            float o10 = acc[f][g][2] + bv.x, o11 = acc[f][g][3] + bv.y;
            if (sizeof(OutT) == 2) {
                __half* Ch = (__half*)Cout;
                *(__half2*)(Ch + (size_t)r * 1024 + c) = __floats2half2_rn(o00, o01);
                *(__half2*)(Ch + (size_t)(r + 8) * 1024 + c) = __floats2half2_rn(o10, o11);
            } else {
                float* Cf = (float*)Cout;
                *(float2*)(Cf + (size_t)r * 1024 + c) = make_float2(o00, o01);
                *(float2*)(Cf + (size_t)(r + 8) * 1024 + c) = make_float2(o10, o11);
            }
        }
    }
}

// ===========================================================================
// MMA sparse attention — unchanged except epilogue writes fp16 ctx
// (the Wo GEMM rounded ctx to fp16 in staging anyway -> zero precision delta)
// ===========================================================================
#define LDKV 136
#define MAXCOLS 384
#define ATTN_SCALE 0.08838834764831845f

__global__ __launch_bounds__(128, 1)
void attn_mma_kernel() {
    __shared__ int colsSm[MAXCOLS];
    __shared__ __align__(16) __half Ksm[64 * LDKV];
    __shared__ __align__(16) __half Vsm[64 * LDKV];

    int tid = threadIdx.x;
    int lane = tid & 31;
    int w = tid >> 5;

    int bid = blockIdx.x;
    int tile = 31 - (bid >> 4);
    int h = bid & 7;
    int b = (bid >> 3) & 1;
    int i0 = tile * 64;
    int cl = (h == 0) ? 0 : (h <= 2) ? 3 : (h <= 5) ? 1 : 2;

    int ncol;
    if (cl == 2) {
        int n16 = ((i0 + 63) >> 4) + 1;
        for (int t = tid; t < n16; t += 128) colsSm[t] = t << 4;
        if (tid < 10) colsSm[n16 + tid] = c_anchors[tid];
        ncol = n16 + 10;
    } else {
        int wr = (cl == 0) ? 8 : (cl == 3) ? 16 : 32;
        int wstart = i0 - wr; if (wstart < 0) wstart = 0;
        int ns = (cl == 1) ? ((wstart + 7) >> 3) : 0;
        int nw = i0 + 63 - wstart + 1;
        if (cl == 1)
            for (int t = tid; t < ns; t += 128) colsSm[t] = t << 3;
        for (int t = tid; t < nw; t += 128) colsSm[ns + t] = wstart + t;
        ncol = ns + nw;
    }
    int npad = (ncol + 63) & ~63;
    for (int t = ncol + tid; t < npad; t += 128) colsSm[t] = 1 << 28;

    {
        int m = tid >> 1;
        int hf = tid & 1;
        const uint4* src = (const uint4*)(g_Qh + ((size_t)(b * L_ + i0 + m)) * E_ + h * D_ + hf * 64);
        uint4* dst = (uint4*)(Ksm + m * LDKV + hf * 64);
#pragma unroll
        for (int t = 0; t < 8; ++t) dst[t] = src[t];
    }
    __syncthreads();

    uint32_t kb = smem_u32(Ksm);
    uint32_t vb = smem_u32(Vsm);

    uint32_t qf[8][4];
    {
        uint32_t aAddr = kb + (uint32_t)(w * 16 + (lane & 15)) * 272 + ((lane >> 4) << 4);
#pragma unroll
        for (int ks = 0; ks < 8; ++ks)
            ldsm4(qf[ks], aAddr + ks * 32);
    }
    __syncthreads();

    float O[16][4];
#pragma unroll
    for (int nb = 0; nb < 16; ++nb)
#pragma unroll
        for (int r = 0; r < 4; ++r) O[nb][r] = 0.0f;
    float sAcc0 = 0.0f, sAcc1 = 0.0f;

    int r_lo = i0 + w * 16 + (lane >> 2);
    int r_hi = r_lo + 8;

    int nchunks = npad >> 6;
    for (int ci = 0; ci < nchunks; ++ci) {
        {
            int slot = tid >> 1;
            int hf = tid & 1;
            int j = colsSm[ci * 64 + slot];
            int jg = (j < L_) ? j : 0;
            size_t go = ((size_t)(b * L_ + jg)) * E_ + h * D_ + hf * 64;
            uint32_t dK = kb + (uint32_t)slot * 272 + hf * 128;
            uint32_t dV = vb + (uint32_t)slot * 272 + hf * 128;
            const __half* sK = g_Kh + go;
            const __half* sV = g_Vh + go;
#pragma unroll
            for (int t = 0; t < 8; ++t) {
                CP16(dK + t * 16, sK + t * 8);
                CP16(dV + t * 16, sV + t * 8);
            }
            asm volatile("cp.async.commit_group;" ::: "memory");
            asm volatile("cp.async.wait_group 0;" ::: "memory");
        }
        __syncthreads();

        float S[8][4];
#pragma unroll
        for (int nb = 0; nb < 8; ++nb)
#pragma unroll
            for (int r = 0; r < 4; ++r) S[nb][r] = 0.0f;

        uint32_t bBase = kb + (uint32_t)((lane & 7) + ((lane >> 4) << 3)) * 272 + (((lane >> 3) & 1) << 4);
#pragma unroll
        for (int g2 = 0; g2 < 4; ++g2) {
#pragma unroll
            for (int ks = 0; ks < 8; ++ks) {
                uint32_t bf[4];
                ldsm4(bf, bBase + (uint32_t)(g2 * 16) * 272 + ks * 32);
                mma_f16(S[g2 * 2 + 0], qf[ks], bf + 0);
                mma_f16(S[g2 * 2 + 1], qf[ks], bf + 2);
            }
        }

        uint32_t aPlo[8], aPhi[8];
#pragma unroll
        for (int nb = 0; nb < 8; ++nb) {
            int cidx = ci * 64 + nb * 8 + ((lane & 3) << 1);
            int j0 = colsSm[cidx];
            int j1 = colsSm[cidx + 1];
            bool ok00, ok01, ok10, ok11;
            if (cl == 0) {
                ok00 = (j0 <= r_lo) && (r_lo - j0 <= 8);
                ok01 = (j1 <= r_lo) && (r_lo - j1 <= 8);
                ok10 = (j0 <= r_hi) && (r_hi - j0 <= 8);
                ok11 = (j1 <= r_hi) && (r_hi - j1 <= 8);
            } else if (cl == 3) {
                ok00 = (j0 <= r_lo) && (r_lo - j0 <= 16);
                ok01 = (j1 <= r_lo) && (r_lo - j1 <= 16);
                ok10 = (j0 <= r_hi) && (r_hi - j0 <= 16);
                ok11 = (j1 <= r_hi) && (r_hi - j1 <= 16);
            } else if (cl == 1) {
                ok00 = (j0 <= r_lo) && ((r_lo - j0 <= 32) || ((j0 & 7) == 0));
                ok01 = (j1 <= r_lo) && ((r_lo - j1 <= 32) || ((j1 & 7) == 0));
                ok10 = (j0 <= r_hi) && ((r_hi - j0 <= 32) || ((j0 & 7) == 0));
                ok11 = (j1 <= r_hi) && ((r_hi - j1 <= 32) || ((j1 & 7) == 0));
            } else {
                ok00 = (j0 <= r_lo);
                ok01 = (j1 <= r_lo);
                ok10 = (j0 <= r_hi);
                ok11 = (j1 <= r_hi);
            }
            float p00 = ok00 ? __expf(fmaf(S[nb][0], ATTN_SCALE, -2.0f)) : 0.0f;
            float p01 = ok01 ? __expf(fmaf(S[nb][1], ATTN_SCALE, -2.0f)) : 0.0f;
            float p10 = ok10 ? __expf(fmaf(S[nb][2], ATTN_SCALE, -2.0f)) : 0.0f;
            float p11 = ok11 ? __expf(fmaf(S[nb][3], ATTN_SCALE, -2.0f)) : 0.0f;
            uint32_t plo = pack_f16x2(p00, p01);
            uint32_t phi = pack_f16x2(p10, p11);
            aPlo[nb] = plo;
            aPhi[nb] = phi;
            float2 rlo = __half22float2(*(__half2*)&plo);
            float2 rhi = __half22float2(*(__half2*)&phi);
            sAcc0 += rlo.x + rlo.y;
            sAcc1 += rhi.x + rhi.y;
        }

#pragma unroll
        for (int ks = 0; ks < 4; ++ks) {
            uint32_t aP[4] = {aPlo[2 * ks], aPhi[2 * ks], aPlo[2 * ks + 1], aPhi[2 * ks + 1]};
            uint32_t vAddr = vb + (uint32_t)(ks * 16 + (lane & 7) + (((lane >> 3) & 1) << 3)) * 272
                           + ((lane >> 4) << 4);
#pragma unroll
            for (int gv = 0; gv < 8; ++gv) {
                uint32_t vf[4];
                ldsm4t(vf, vAddr + gv * 32);
                mma_f16(O[gv * 2 + 0], aP, vf + 0);
                mma_f16(O[gv * 2 + 1], aP, vf + 2);
            }
        }
        __syncthreads();
    }

    sAcc0 += __shfl_xor_sync(0xffffffffu, sAcc0, 1);
    sAcc0 += __shfl_xor_sync(0xffffffffu, sAcc0, 2);
    sAcc1 += __shfl_xor_sync(0xffffffffu, sAcc1, 1);
    sAcc1 += __shfl_xor_sync(0xffffffffu, sAcc1, 2);
    float inv0 = 1.0f / sAcc0;
    float inv1 = 1.0f / sAcc1;

    __half* out0 = g_Ch + ((size_t)(b * L_ + r_lo)) * E_ + h * D_;
    __half* out1 = g_Ch + ((size_t)(b * L_ + r_hi)) * E_ + h * D_;
#pragma unroll
    for (int nb = 0; nb < 16; ++nb) {
        int col = nb * 8 + ((lane & 3) << 1);
        *(__half2*)(out0 + col) = __floats2half2_rn(O[nb][0] * inv0, O[nb][1] * inv0);
        *(__half2*)(out1 + col) = __floats2half2_rn(O[nb][2] * inv1, O[nb][3] * inv1);
    }
}

// ---------------------------------------------------------------------------
extern "C" void kernel_launch(void* const* d_in, const int* in_sizes, int n_in,
                              void* d_out, int out_size) {
    const float* query = (const float*)d_in[0];
    const float* key_  = (const float*)d_in[1];
    const float* value = (const float*)d_in[2];
    const float* Wq = (const float*)d_in[3];
    const float* bq = (const float*)d_in[4];
    const float* Wk = (const float*)d_in[5];
    const float* bk = (const float*)d_in[6];
    const float* Wv = (const float*)d_in[7];
    const float* bv = (const float*)d_in[8];
    const float* Wo = (const float*)d_in[9];
    const float* bo = (const float*)d_in[10];
    float* out = (float*)d_out;

    __half *Aq, *Ak, *Av, *Wqh, *Wkh, *Wvh, *Woh, *Qhd, *Khd, *Vhd, *Chd;
    cudaGetSymbolAddress((void**)&Aq, g_Aq);
    cudaGetSymbolAddress((void**)&Ak, g_Ak);
    cudaGetSymbolAddress((void**)&Av, g_Av);
    cudaGetSymbolAddress((void**)&Wqh, g_Wqh);
    cudaGetSymbolAddress((void**)&Wkh, g_Wkh);
    cudaGetSymbolAddress((void**)&Wvh, g_Wvh);
    cudaGetSymbolAddress((void**)&Woh, g_Woh);
    cudaGetSymbolAddress((void**)&Qhd, g_Qh);
    cudaGetSymbolAddress((void**)&Khd, g_Kh);
    cudaGetSymbolAddress((void**)&Vhd, g_Vh);
    cudaGetSymbolAddress((void**)&Chd, g_Ch);

    // 1. convert everything to fp16 (one launch, 16M floats)
    convert_all_kernel<<<(3 * N_ACT + 4 * N_WT) / 256, 256>>>(
        (const float4*)query, (const float4*)key_, (const float4*)value,
        (const float4*)Wq, (const float4*)Wk, (const float4*)Wv, (const float4*)Wo,
        (uint2*)Aq, (uint2*)Ak, (uint2*)Av,
        (uint2*)Wqh, (uint2*)Wkh, (uint2*)Wvh, (uint2*)Woh);

    dim3 ggrid(E_ / 128, (B_ * L_) / 128);   // 8 x 32 = 256 CTAs

    gemm_h_kernel<__half><<<ggrid, 256>>>(Aq, Wqh, bq, Qhd);
    gemm_h_kernel<__half><<<ggrid, 256>>>(Ak, Wkh, bk, Khd);
    gemm_h_kernel<__half><<<ggrid, 256>>>(Av, Wvh, bv, Vhd);

    attn_mma_kernel<<<B_ * H_ * (L_ / 64), 128>>>();   // 512 CTAs

    gemm_h_kernel<float><<<ggrid, 256>>>(Chd, Woh, bo, out);
}

// round 17
// speedup vs baseline: 1.0353x; 1.0353x over previous
#include <cuda_runtime.h>
#include <cuda_fp16.h>
#include <cstdint>
#include <math.h>

#define B_ 2
#define L_ 2048
#define E_ 1024
#define H_ 8
#define D_ 128

// Scratch (allocation-free rule: __device__ globals)
__device__ __half g_Aq[B_ * L_ * E_];   // fp16 copies of activations
__device__ __half g_Ak[B_ * L_ * E_];
__device__ __half g_Av[B_ * L_ * E_];
__device__ __half g_Wqh[E_ * E_];       // fp16 copies of weights
__device__ __half g_Wkh[E_ * E_];
__device__ __half g_Wvh[E_ * E_];
__device__ __half g_Woh[E_ * E_];
__device__ __half g_Qh[B_ * L_ * E_];   // projection outputs
__device__ __half g_Kh[B_ * L_ * E_];
__device__ __half g_Vh[B_ * L_ * E_];
__device__ __half g_Ch[B_ * L_ * E_];   // attention context (fp16)

__constant__ int c_anchors[10] = {204, 409, 614, 781, 1023, 1265, 1432, 1637, 1842, 2047};

// ===========================================================================
// helpers
// ===========================================================================
__device__ __forceinline__ uint32_t smem_u32(const void* p) {
    uint32_t a;
    asm("{ .reg .u64 t; cvta.to.shared.u64 t, %1; cvt.u32.u64 %0, t; }" : "=r"(a) : "l"(p));
    return a;
}

__device__ __forceinline__ uint32_t pack_f16x2(float x0, float x1) {
    uint32_t r;
    asm("cvt.rn.f16x2.f32 %0, %2, %1;" : "=r"(r) : "f"(x0), "f"(x1));
    return r;
}

__device__ __forceinline__ void ldsm4(uint32_t* r, uint32_t addr) {
    asm volatile("ldmatrix.sync.aligned.m8n8.x4.shared.b16 {%0,%1,%2,%3}, [%4];"
                 : "=r"(r[0]), "=r"(r[1]), "=r"(r[2]), "=r"(r[3]) : "r"(addr));
}

__device__ __forceinline__ void ldsm4t(uint32_t* r, uint32_t addr) {
    asm volatile("ldmatrix.sync.aligned.m8n8.x4.trans.shared.b16 {%0,%1,%2,%3}, [%4];"
                 : "=r"(r[0]), "=r"(r[1]), "=r"(r[2]), "=r"(r[3]) : "r"(addr));
}

__device__ __forceinline__ void mma_f16(float* d, const uint32_t* a, const uint32_t* b) {
    asm volatile(
        "mma.sync.aligned.m16n8k16.row.col.f32.f16.f16.f32 "
        "{%0,%1,%2,%3}, {%4,%5,%6,%7}, {%8,%9}, {%0,%1,%2,%3};"
        : "+f"(d[0]), "+f"(d[1]), "+f"(d[2]), "+f"(d[3])
        : "r"(a[0]), "r"(a[1]), "r"(a[2]), "r"(a[3]), "r"(b[0]), "r"(b[1]));
}

#define CP16(dst, src) \
    asm volatile("cp.async.cg.shared.global [%0], [%1], 16;" :: "r"(dst), "l"(src) : "memory")

// ===========================================================================
// Mega-convert: all fp32 inputs -> fp16 in one launch (16M floats).
// ===========================================================================
#define N_ACT  1048576           // float4 count per activation
#define N_WT   262144            // float4 count per weight

__global__ __launch_bounds__(256)
void convert_all_kernel(const float4* __restrict__ q, const float4* __restrict__ k,
                        const float4* __restrict__ v, const float4* __restrict__ wq,
                        const float4* __restrict__ wk, const float4* __restrict__ wv,
                        const float4* __restrict__ wo,
                        uint2* __restrict__ aq, uint2* __restrict__ ak, uint2* __restrict__ av,
                        uint2* __restrict__ wqh, uint2* __restrict__ wkh,
                        uint2* __restrict__ wvh, uint2* __restrict__ woh) {
    int i = blockIdx.x * 256 + threadIdx.x;
    const float4* src; uint2* dst; int off;
    if (i < 3 * N_ACT) {
        if (i < N_ACT)            { src = q; dst = aq; off = i; }
        else if (i < 2 * N_ACT)   { src = k; dst = ak; off = i - N_ACT; }
        else                      { src = v; dst = av; off = i - 2 * N_ACT; }
    } else {
        int j = i - 3 * N_ACT;
        if (j < N_WT)             { src = wq; dst = wqh; off = j; }
        else if (j < 2 * N_WT)    { src = wk; dst = wkh; off = j - N_WT; }
        else if (j < 3 * N_WT)    { src = wv; dst = wvh; off = j - 2 * N_WT; }
        else                      { src = wo; dst = woh; off = j - 3 * N_WT; }
    }
    float4 x = src[off];
    dst[off] = make_uint2(pack_f16x2(x.x, x.y), pack_f16x2(x.z, x.w));
}

// ===========================================================================
// GEMM v4: fp16 inputs, 4-stage cp.async ring, ONE barrier per chunk, occ 2.
//   C = A @ W^T + bias.  CTA 128x128, 8 warps (2m x 4n), BK=32.
// Stage = A(10240B) + W(10240B) = 20480B; 4 stages = 81920B dynamic smem.
// Order per chunk: wait_group -> sync (publishes kt, protects kt-1's buffer)
//                  -> stage(kt+3) -> compute(kt).
// ===========================================================================
#define LDA 80
#define OP_B 10240
#define STAGE_B 20480
#define GSMEM (4 * STAGE_B)      // 81920

template <typename OutT>
__global__ __launch_bounds__(256, 2)
void gemm_h_kernel(const __half* __restrict__ A, const __half* __restrict__ W,
                   const float* __restrict__ bias, OutT* __restrict__ Cout) {
    extern __shared__ __align__(16) uint8_t sm[];
    uint32_t sb = smem_u32(sm);

    int tid = threadIdx.x;
    int lane = tid & 31;
    int wid = tid >> 5;
    int warpM = wid >> 2;
    int warpN = wid & 3;

    const __half* Ag = A + (size_t)blockIdx.y * 128 * 1024;
    const __half* Wg = W + (size_t)blockIdx.x * 128 * 1024;

    int srow = tid >> 1;         // 0..127
    int hf = tid & 1;            // which 32B half of the 64B row

    float acc[4][4][4];
#pragma unroll
    for (int f = 0; f < 4; ++f)
#pragma unroll
        for (int g = 0; g < 4; ++g)
#pragma unroll
            for (int r = 0; r < 4; ++r) acc[f][g][r] = 0.0f;

    uint32_t aRow = (uint32_t)(warpM * 64) + (lane & 15);
    uint32_t aAddrBase = aRow * LDA + ((lane >> 4) << 4);
    uint32_t bRow = (uint32_t)(warpN * 32) + (lane & 7) + ((lane >> 4) << 3);
    uint32_t bAddrBase = bRow * LDA + (((lane >> 3) & 1) << 4);

    auto stage = [&](int kt) {
        int st = kt & 3;
        uint32_t dA = sb + (uint32_t)st * STAGE_B + (uint32_t)srow * LDA + hf * 32;
        uint32_t dW = dA + OP_B;
        const __half* sA = Ag + (size_t)srow * 1024 + kt * 32 + hf * 16;
        const __half* sW = Wg + (size_t)srow * 1024 + kt * 32 + hf * 16;
        CP16(dA, sA); CP16(dA + 16, sA + 8);
        CP16(dW, sW); CP16(dW + 16, sW + 8);
        asm volatile("cp.async.commit_group;" ::: "memory");
    };

    stage(0); stage(1); stage(2);

    for (int kt = 0; kt < 32; ++kt) {
        // wait until chunk kt's group is complete (allow the newest <=2 pending)
        int allow = 31 - kt; if (allow > 2) allow = 2;
        if (allow == 2)      asm volatile("cp.async.wait_group 2;" ::: "memory");
        else if (allow == 1) asm volatile("cp.async.wait_group 1;" ::: "memory");
        else                 asm volatile("cp.async.wait_group 0;" ::: "memory");
        __syncthreads();     // publish kt's data; all readers of chunk kt-1 done

        if (kt + 3 < 32)
            stage(kt + 3);   // overwrites buffer (kt-1)&3 — safe after the sync

        uint32_t sbA = sb + (uint32_t)(kt & 3) * STAGE_B;
        uint32_t sbW = sbA + OP_B;
#pragma unroll
        for (int ks = 0; ks < 2; ++ks) {
            uint32_t koff = ks * 32;
            uint32_t bF[2][4];
            ldsm4(bF[0], sbW + bAddrBase + koff);
            ldsm4(bF[1], sbW + bAddrBase + 16 * LDA + koff);
#pragma unroll
            for (int f = 0; f < 4; ++f) {
                uint32_t aF[4];
                ldsm4(aF, sbA + aAddrBase + (uint32_t)(f * 16) * LDA + koff);
#pragma unroll
                for (int g = 0; g < 4; ++g)
                    mma_f16(acc[f][g], aF, &bF[g >> 1][(g & 1) * 2]);
            }
        }
    }

    int crow = blockIdx.y * 128 + warpM * 64 + (lane >> 2);
    int ccol0 = blockIdx.x * 128 + warpN * 32 + (lane & 3) * 2;
#pragma unroll
    for (int g = 0; g < 4; ++g) {
        int c = ccol0 + g * 8;
        float2 bv = *(const float2*)(bias + c);
#pragma unroll
        for (int f = 0; f < 4; ++f) {
            int r = crow + f * 16;
            float o00 = acc[f][g][0] + bv.x, o01 = acc[f][g][1] + bv.y;
            float o10 = acc[f][g][2] + bv.x, o11 = acc[f][g][3] + bv.y;
            if (sizeof(OutT) == 2) {
                __half* Ch = (__half*)Cout;
                *(__half2*)(Ch + (size_t)r * 1024 + c) = __floats2half2_rn(o00, o01);
                *(__half2*)(Ch + (size_t)(r + 8) * 1024 + c) = __floats2half2_rn(o10, o11);
            } else {
                float* Cf = (float*)Cout;
                *(float2*)(Cf + (size_t)r * 1024 + c) = make_float2(o00, o01);
                *(float2*)(Cf + (size_t)(r + 8) * 1024 + c) = make_float2(o10, o11);
            }
        }
    }
}

// ===========================================================================
// MMA sparse attention (R16, passing — unchanged; fp16 ctx output)
// ===========================================================================
#define LDKV 136
#define MAXCOLS 384
#define ATTN_SCALE 0.08838834764831845f

__global__ __launch_bounds__(128, 1)
void attn_mma_kernel() {
    __shared__ int colsSm[MAXCOLS];
    __shared__ __align__(16) __half Ksm[64 * LDKV];
    __shared__ __align__(16) __half Vsm[64 * LDKV];

    int tid = threadIdx.x;
    int lane = tid & 31;
    int w = tid >> 5;

    int bid = blockIdx.x;
    int tile = 31 - (bid >> 4);
    int h = bid & 7;
    int b = (bid >> 3) & 1;
    int i0 = tile * 64;
    int cl = (h == 0) ? 0 : (h <= 2) ? 3 : (h <= 5) ? 1 : 2;

    int ncol;
    if (cl == 2) {
        int n16 = ((i0 + 63) >> 4) + 1;
        for (int t = tid; t < n16; t += 128) colsSm[t] = t << 4;
        if (tid < 10) colsSm[n16 + tid] = c_anchors[tid];
        ncol = n16 + 10;
    } else {
        int wr = (cl == 0) ? 8 : (cl == 3) ? 16 : 32;
        int wstart = i0 - wr; if (wstart < 0) wstart = 0;
        int ns = (cl == 1) ? ((wstart + 7) >> 3) : 0;
        int nw = i0 + 63 - wstart + 1;
        if (cl == 1)
            for (int t = tid; t < ns; t += 128) colsSm[t] = t << 3;
        for (int t = tid; t < nw; t += 128) colsSm[ns + t] = wstart + t;
        ncol = ns + nw;
    }
    int npad = (ncol + 63) & ~63;
    for (int t = ncol + tid; t < npad; t += 128) colsSm[t] = 1 << 28;

    {
        int m = tid >> 1;
        int hf = tid & 1;
        const uint4* src = (const uint4*)(g_Qh + ((size_t)(b * L_ + i0 + m)) * E_ + h * D_ + hf * 64);
        uint4* dst = (uint4*)(Ksm + m * LDKV + hf * 64);
#pragma unroll
        for (int t = 0; t < 8; ++t) dst[t] = src[t];
    }
    __syncthreads();

    uint32_t kb = smem_u32(Ksm);
    uint32_t vb = smem_u32(Vsm);

    uint32_t qf[8][4];
    {
        uint32_t aAddr = kb + (uint32_t)(w * 16 + (lane & 15)) * 272 + ((lane >> 4) << 4);
#pragma unroll
        for (int ks = 0; ks < 8; ++ks)
            ldsm4(qf[ks], aAddr + ks * 32);
    }
    __syncthreads();

    float O[16][4];
#pragma unroll
    for (int nb = 0; nb < 16; ++nb)
#pragma unroll
        for (int r = 0; r < 4; ++r) O[nb][r] = 0.0f;
    float sAcc0 = 0.0f, sAcc1 = 0.0f;

    int r_lo = i0 + w * 16 + (lane >> 2);
    int r_hi = r_lo + 8;

    int nchunks = npad >> 6;
    for (int ci = 0; ci < nchunks; ++ci) {
        {
            int slot = tid >> 1;
            int hf = tid & 1;
            int j = colsSm[ci * 64 + slot];
            int jg = (j < L_) ? j : 0;
            size_t go = ((size_t)(b * L_ + jg)) * E_ + h * D_ + hf * 64;
            uint32_t dK = kb + (uint32_t)slot * 272 + hf * 128;
            uint32_t dV = vb + (uint32_t)slot * 272 + hf * 128;
            const __half* sK = g_Kh + go;
            const __half* sV = g_Vh + go;
#pragma unroll
            for (int t = 0; t < 8; ++t) {
                CP16(dK + t * 16, sK + t * 8);
                CP16(dV + t * 16, sV + t * 8);
            }
            asm volatile("cp.async.commit_group;" ::: "memory");
            asm volatile("cp.async.wait_group 0;" ::: "memory");
        }
        __syncthreads();

        float S[8][4];
#pragma unroll
        for (int nb = 0; nb < 8; ++nb)
#pragma unroll
            for (int r = 0; r < 4; ++r) S[nb][r] = 0.0f;

        uint32_t bBase = kb + (uint32_t)((lane & 7) + ((lane >> 4) << 3)) * 272 + (((lane >> 3) & 1) << 4);
#pragma unroll
        for (int g2 = 0; g2 < 4; ++g2) {
#pragma unroll
            for (int ks = 0; ks < 8; ++ks) {
                uint32_t bf[4];
                ldsm4(bf, bBase + (uint32_t)(g2 * 16) * 272 + ks * 32);
                mma_f16(S[g2 * 2 + 0], qf[ks], bf + 0);
                mma_f16(S[g2 * 2 + 1], qf[ks], bf + 2);
            }
        }

        uint32_t aPlo[8], aPhi[8];
#pragma unroll
        for (int nb = 0; nb < 8; ++nb) {
            int cidx = ci * 64 + nb * 8 + ((lane & 3) << 1);
            int j0 = colsSm[cidx];
            int j1 = colsSm[cidx + 1];
            bool ok00, ok01, ok10, ok11;
            if (cl == 0) {
                ok00 = (j0 <= r_lo) && (r_lo - j0 <= 8);
                ok01 = (j1 <= r_lo) && (r_lo - j1 <= 8);
                ok10 = (j0 <= r_hi) && (r_hi - j0 <= 8);
                ok11 = (j1 <= r_hi) && (r_hi - j1 <= 8);
            } else if (cl == 3) {
                ok00 = (j0 <= r_lo) && (r_lo - j0 <= 16);
                ok01 = (j1 <= r_lo) && (r_lo - j1 <= 16);
                ok10 = (j0 <= r_hi) && (r_hi - j0 <= 16);
                ok11 = (j1 <= r_hi) && (r_hi - j1 <= 16);
            } else if (cl == 1) {
                ok00 = (j0 <= r_lo) && ((r_lo - j0 <= 32) || ((j0 & 7) == 0));
                ok01 = (j1 <= r_lo) && ((r_lo - j1 <= 32) || ((j1 & 7) == 0));
                ok10 = (j0 <= r_hi) && ((r_hi - j0 <= 32) || ((j0 & 7) == 0));
                ok11 = (j1 <= r_hi) && ((r_hi - j1 <= 32) || ((j1 & 7) == 0));
            } else {
                ok00 = (j0 <= r_lo);
                ok01 = (j1 <= r_lo);
                ok10 = (j0 <= r_hi);
                ok11 = (j1 <= r_hi);
            }
            float p00 = ok00 ? __expf(fmaf(S[nb][0], ATTN_SCALE, -2.0f)) : 0.0f;
            float p01 = ok01 ? __expf(fmaf(S[nb][1], ATTN_SCALE, -2.0f)) : 0.0f;
            float p10 = ok10 ? __expf(fmaf(S[nb][2], ATTN_SCALE, -2.0f)) : 0.0f;
            float p11 = ok11 ? __expf(fmaf(S[nb][3], ATTN_SCALE, -2.0f)) : 0.0f;
            uint32_t plo = pack_f16x2(p00, p01);
            uint32_t phi = pack_f16x2(p10, p11);
            aPlo[nb] = plo;
            aPhi[nb] = phi;
            float2 rlo = __half22float2(*(__half2*)&plo);
            float2 rhi = __half22float2(*(__half2*)&phi);
            sAcc0 += rlo.x + rlo.y;
            sAcc1 += rhi.x + rhi.y;
        }

#pragma unroll
        for (int ks = 0; ks < 4; ++ks) {
            uint32_t aP[4] = {aPlo[2 * ks], aPhi[2 * ks], aPlo[2 * ks + 1], aPhi[2 * ks + 1]};
            uint32_t vAddr = vb + (uint32_t)(ks * 16 + (lane & 7) + (((lane >> 3) & 1) << 3)) * 272
                           + ((lane >> 4) << 4);
#pragma unroll
            for (int gv = 0; gv < 8; ++gv) {
                uint32_t vf[4];
                ldsm4t(vf, vAddr + gv * 32);
                mma_f16(O[gv * 2 + 0], aP, vf + 0);
                mma_f16(O[gv * 2 + 1], aP, vf + 2);
            }
        }
        __syncthreads();
    }

    sAcc0 += __shfl_xor_sync(0xffffffffu, sAcc0, 1);
    sAcc0 += __shfl_xor_sync(0xffffffffu, sAcc0, 2);
    sAcc1 += __shfl_xor_sync(0xffffffffu, sAcc1, 1);
    sAcc1 += __shfl_xor_sync(0xffffffffu, sAcc1, 2);
    float inv0 = 1.0f / sAcc0;
    float inv1 = 1.0f / sAcc1;

    __half* out0 = g_Ch + ((size_t)(b * L_ + r_lo)) * E_ + h * D_;
    __half* out1 = g_Ch + ((size_t)(b * L_ + r_hi)) * E_ + h * D_;
#pragma unroll
    for (int nb = 0; nb < 16; ++nb) {
        int col = nb * 8 + ((lane & 3) << 1);
        *(__half2*)(out0 + col) = __floats2half2_rn(O[nb][0] * inv0, O[nb][1] * inv0);
        *(__half2*)(out1 + col) = __floats2half2_rn(O[nb][2] * inv1, O[nb][3] * inv1);
    }
}

// ---------------------------------------------------------------------------
extern "C" void kernel_launch(void* const* d_in, const int* in_sizes, int n_in,
                              void* d_out, int out_size) {
    const float* query = (const float*)d_in[0];
    const float* key_  = (const float*)d_in[1];
    const float* value = (const float*)d_in[2];
    const float* Wq = (const float*)d_in[3];
    const float* bq = (const float*)d_in[4];
    const float* Wk = (const float*)d_in[5];
    const float* bk = (const float*)d_in[6];
    const float* Wv = (const float*)d_in[7];
    const float* bv = (const float*)d_in[8];
    const float* Wo = (const float*)d_in[9];
    const float* bo = (const float*)d_in[10];
    float* out = (float*)d_out;

    __half *Aq, *Ak, *Av, *Wqh, *Wkh, *Wvh, *Woh, *Qhd, *Khd, *Vhd, *Chd;
    cudaGetSymbolAddress((void**)&Aq, g_Aq);
    cudaGetSymbolAddress((void**)&Ak, g_Ak);
    cudaGetSymbolAddress((void**)&Av, g_Av);
    cudaGetSymbolAddress((void**)&Wqh, g_Wqh);
    cudaGetSymbolAddress((void**)&Wkh, g_Wkh);
    cudaGetSymbolAddress((void**)&Wvh, g_Wvh);
    cudaGetSymbolAddress((void**)&Woh, g_Woh);
    cudaGetSymbolAddress((void**)&Qhd, g_Qh);
    cudaGetSymbolAddress((void**)&Khd, g_Kh);
    cudaGetSymbolAddress((void**)&Vhd, g_Vh);
    cudaGetSymbolAddress((void**)&Chd, g_Ch);

    cudaFuncSetAttribute(gemm_h_kernel<__half>,
                         cudaFuncAttributeMaxDynamicSharedMemorySize, GSMEM);
    cudaFuncSetAttribute(gemm_h_kernel<float>,
                         cudaFuncAttributeMaxDynamicSharedMemorySize, GSMEM);

    convert_all_kernel<<<(3 * N_ACT + 4 * N_WT) / 256, 256>>>(
        (const float4*)query, (const float4*)key_, (const float4*)value,
        (const float4*)Wq, (const float4*)Wk, (const float4*)Wv, (const float4*)Wo,
        (uint2*)Aq, (uint2*)Ak, (uint2*)Av,
        (uint2*)Wqh, (uint2*)Wkh, (uint2*)Wvh, (uint2*)Woh);

    dim3 ggrid(E_ / 128, (B_ * L_) / 128);   // 8 x 32 = 256 CTAs

    gemm_h_kernel<__half><<<ggrid, 256, GSMEM>>>(Aq, Wqh, bq, Qhd);
    gemm_h_kernel<__half><<<ggrid, 256, GSMEM>>>(Ak, Wkh, bk, Khd);
    gemm_h_kernel<__half><<<ggrid, 256, GSMEM>>>(Av, Wvh, bv, Vhd);

    attn_mma_kernel<<<B_ * H_ * (L_ / 64), 128>>>();   // 512 CTAs

    gemm_h_kernel<float><<<ggrid, 256, GSMEM>>>(Chd, Woh, bo, out);
}